// round 14
// baseline (speedup 1.0000x reference)
#include <cuda_runtime.h>
#include <cstdint>

#define BS   128
#define T    512
#define E    512
#define NGRP 8          // batch groups
#define RPG  16         // batch rows per group
#define CPG  16         // CTAs per group (column split)
#define NC   32         // output cols per CTA
#define NTHR 512
#define XPAD 36         // padded row stride of warp-private x tile
#define XWRP (16 * XPAD)// floats per warp tile (576)

// output layout offsets (float elements)
#define ACT_OFF  0
#define EC3HIS   131072
#define EC5HIS   33685504
#define CA1HIS   67239936
#define EC3F     100794368
#define EC5F     100859904
#define CA1F     100925440

// device scratch
__device__ float    g_drive[T * E];
__device__ float    g_ex_ca1[BS * E];
__device__ float    g_ex_ec3[BS * E];
__device__ float    g_ex_act[BS * CPG * 2];   // per-CTA act partials
__device__ unsigned g_bar_cnt[16];
__device__ unsigned g_bar_gen[16];
__device__ unsigned g_flagA[NGRP * CPG];      // per-producer phase-A flags
__device__ unsigned g_flagB[NGRP * CPG];      // per-producer phase-B flags
__device__ int      g_scan[128];

// smem layout (floats)
#define SM_W1    0
#define SM_W2    (512 * NC)                  // 16384
#define SM_X     (2 * 512 * NC)              // 32768 (16 warp tiles x 576)
#define SM_RED   (SM_X + 16 * XWRP)          // 41984 (8192 floats)
#define SM_FLOATS (SM_RED + 8192)            // 50176
#define SMEM_BYTES (SM_FLOATS * 4)           // 200704 B

__device__ __forceinline__ unsigned long long pack2(float x) {
    unsigned long long r;
    asm("mov.b64 %0, {%1, %1};" : "=l"(r) : "f"(x));
    return r;
}
__device__ __forceinline__ void fma2(unsigned long long& d,
                                     unsigned long long a, unsigned long long b) {
    asm("fma.rn.f32x2 %0, %1, %2, %0;" : "+l"(d) : "l"(a), "l"(b));
}

// full-grid sense-reversal barrier (once, after phase 0; 128 CTAs co-resident)
__device__ __forceinline__ void grid_barrier(int idx, unsigned n) {
    __syncthreads();
    if (threadIdx.x == 0) {
        __threadfence();
        volatile unsigned* vgen = g_bar_gen;
        unsigned gen0 = vgen[idx];
        unsigned a = atomicAdd(&g_bar_cnt[idx], 1u);
        if (a == n - 1u) {
            g_bar_cnt[idx] = 0u;
            __threadfence();
            vgen[idx] = gen0 + 1u;
        } else {
            while (vgen[idx] == gen0) { }
        }
        __threadfence();
    }
    __syncthreads();
}

// producer publish: whole-CTA stores done -> release -> single-writer flag
__device__ __forceinline__ void publish(volatile unsigned* myflag, unsigned val) {
    __syncthreads();
    if (threadIdx.x == 0) {
        __threadfence();
        *myflag = val;
    }
}

// z[16][32] = X(16 x 512, global exchange) @ Ws(512 x 32, smem), per-producer
// flag sync. Warp w: poll flags[w] >= target (lane0 only), gather its own
// 16x32 slice (cols [32w,32w+32)) into a warp-private padded smem tile,
// register-tile FMA, write partial; CTA sync; single-pass reduction.
// Arithmetic identical to the monolithic-barrier version.
__device__ __forceinline__ float gemm_flag(const float* __restrict__ Ws,
                                           const float* __restrict__ xg,
                                           volatile const unsigned* flags,
                                           unsigned target,
                                           float* __restrict__ xs,
                                           float* __restrict__ red) {
    const int tid  = threadIdx.x;
    const int warp = tid >> 5, lane = tid & 31;
    const int rg = lane >> 3, cg = lane & 7;

    // wait for this warp's producer only
    if (lane == 0) {
        while (flags[warp] < target) { }
    }
    __syncwarp();

    // warp-private gather: rows 0..15 of cols [32w, 32w+32)
    float* xw = xs + warp * XWRP;
    {
        const float* src = xg + (warp << 5);
#pragma unroll
        for (int h = 0; h < 4; h++) {
            int f   = h * 32 + lane;
            int row = f >> 3, c4 = (f & 7) << 2;
            float4 v = __ldcg((const float4*)(src + row * 512 + c4));
            *(float4*)(xw + row * XPAD + c4) = v;
        }
        __syncwarp();
    }

    const float* xb = xw + rg * XPAD;
    const ulonglong2* wb = (const ulonglong2*)(Ws + (warp << 5) * NC + (cg << 2));

    unsigned long long a00=0ull,a01=0ull,a10=0ull,a11=0ull,
                       a20=0ull,a21=0ull,a30=0ull,a31=0ull;
#pragma unroll
    for (int kb = 0; kb < 32; kb += 4) {
        float4 x0 = *(const float4*)(xb + 0 * 4 * XPAD + kb);
        float4 x1 = *(const float4*)(xb + 1 * 4 * XPAD + kb);
        float4 x2 = *(const float4*)(xb + 2 * 4 * XPAD + kb);
        float4 x3 = *(const float4*)(xb + 3 * 4 * XPAD + kb);
        ulonglong2 w0 = wb[(kb + 0) * 8];
        ulonglong2 w1 = wb[(kb + 1) * 8];
        ulonglong2 w2 = wb[(kb + 2) * 8];
        ulonglong2 w3 = wb[(kb + 3) * 8];
        unsigned long long p;
        p = pack2(x0.x); fma2(a00, p, w0.x); fma2(a01, p, w0.y);
        p = pack2(x0.y); fma2(a00, p, w1.x); fma2(a01, p, w1.y);
        p = pack2(x0.z); fma2(a00, p, w2.x); fma2(a01, p, w2.y);
        p = pack2(x0.w); fma2(a00, p, w3.x); fma2(a01, p, w3.y);
        p = pack2(x1.x); fma2(a10, p, w0.x); fma2(a11, p, w0.y);
        p = pack2(x1.y); fma2(a10, p, w1.x); fma2(a11, p, w1.y);
        p = pack2(x1.z); fma2(a10, p, w2.x); fma2(a11, p, w2.y);
        p = pack2(x1.w); fma2(a10, p, w3.x); fma2(a11, p, w3.y);
        p = pack2(x2.x); fma2(a20, p, w0.x); fma2(a21, p, w0.y);
        p = pack2(x2.y); fma2(a20, p, w1.x); fma2(a21, p, w1.y);
        p = pack2(x2.z); fma2(a20, p, w2.x); fma2(a21, p, w2.y);
        p = pack2(x2.w); fma2(a20, p, w3.x); fma2(a21, p, w3.y);
        p = pack2(x3.x); fma2(a30, p, w0.x); fma2(a31, p, w0.y);
        p = pack2(x3.y); fma2(a30, p, w1.x); fma2(a31, p, w1.y);
        p = pack2(x3.z); fma2(a30, p, w2.x); fma2(a31, p, w2.y);
        p = pack2(x3.w); fma2(a30, p, w3.x); fma2(a31, p, w3.y);
    }

    unsigned long long* buf64 = (unsigned long long*)red;
    {
        unsigned long long* d = buf64 + (warp << 8) + rg * 16 + cg * 2;
        ulonglong2 v;
        v.x = a00; v.y = a01; *(ulonglong2*)(d)       = v;
        v.x = a10; v.y = a11; *(ulonglong2*)(d + 64)  = v;
        v.x = a20; v.y = a21; *(ulonglong2*)(d + 128) = v;
        v.x = a30; v.y = a31; *(ulonglong2*)(d + 192) = v;
    }
    __syncthreads();
    const int o = tid;
    float s0 = red[o]        + red[512  + o];
    float s1 = red[1024 + o] + red[1536 + o];
    float s2 = red[2048 + o] + red[2560 + o];
    float s3 = red[3072 + o] + red[3584 + o];
    float s4 = red[4096 + o] + red[4608 + o];
    float s5 = red[5120 + o] + red[5632 + o];
    float s6 = red[6144 + o] + red[6656 + o];
    float s7 = red[7168 + o] + red[7680 + o];
    return ((s0 + s1) + (s2 + s3)) + ((s4 + s5) + (s6 + s7));
}

__global__ void __launch_bounds__(NTHR, 1)
rnn_kernel(const float* __restrict__ ec3input,
           const float* __restrict__ ec3_last,
           const float* __restrict__ ec5_last,
           const float* __restrict__ ca1_last,
           const float* __restrict__ ca1bias,
           const float* __restrict__ wca3ca1,
           const float* __restrict__ wec3ca1,
           const float* __restrict__ wca1ec5,
           const float* __restrict__ wca1act,
           const float* __restrict__ actbias,
           const void* __restrict__ noise_mask,
           const int* __restrict__ ca3order,
           float* __restrict__ out) {
    extern __shared__ float smem[];
    float* W1s = smem + SM_W1;
    float* W2s = smem + SM_W2;
    float* x_s = smem + SM_X;
    float* red = smem + SM_RED;
    __shared__ int s_mmode;

    const int tid = threadIdx.x;
    const int bx  = blockIdx.x;
    const int g   = bx >> 4;
    const int ci  = bx & 15;
    const int j0  = ci * NC;
    const int r   = tid >> 5;        // row 0..15
    const int j   = tid & 31;
    const int lane = tid & 31;
    const int b   = g * RPG + r;
    const int col = j0 + j;

    // reset own flags + stage ec3_last into the exchange buffer
    // (flagB = 1 means "ec3 state for step 0 available")
    if (tid == 0) { g_flagA[bx] = 0u; g_flagB[bx] = 1u; }
    g_ex_ec3[b * 512 + col] = ec3_last[b * 512 + col];

    // ---------------- Phase 0a: mask-dtype scan ----------------
    if (tid == 0) g_scan[bx] = 0;
    __syncthreads();
    {
        const uint4* mw = (const uint4*)noise_mask;
        int bits = 0;
#pragma unroll
        for (int u = 0; u < 16; u++) {
            uint4 w = __ldcg(&mw[(size_t)bx * 8192 + (size_t)u * 512 + tid]);
            unsigned ws[4] = {w.x, w.y, w.z, w.w};
#pragma unroll
            for (int e = 0; e < 4; e++) {
                unsigned v = ws[e];
                if (v) {
                    if (v == 1u)               bits |= 2;
                    else if (v == 0x3F800000u) bits |= 4;
                    else                       bits |= 1;
                }
            }
        }
        if (bits) atomicOr(&g_scan[bx], bits);
    }

    // ---------------- Phase 0b: ca3drive precompute ----------------
    {
        float* ca3v = red;               // scratch
        const float stepv = 614.4f / 511.0f;
        const int   ordc  = ca3order[tid];
        const float cen   = -51.2f + stepv * (float)ordc;
#pragma unroll
        for (int i = 0; i < 4; i++) {
            float d = cen - (float)(4 * bx + i);
            ca3v[i * 512 + tid] = expf(-d * d * 0.02f);
        }
        __syncthreads();
        float a0 = 0.f, a1 = 0.f, a2 = 0.f, a3 = 0.f;
#pragma unroll 4
        for (int c = 0; c < 512; c++) {
            float wv = wca3ca1[c * 512 + tid];
            a0 = fmaf(ca3v[c],        wv, a0);
            a1 = fmaf(ca3v[512 + c],  wv, a1);
            a2 = fmaf(ca3v[1024 + c], wv, a2);
            a3 = fmaf(ca3v[1536 + c], wv, a3);
        }
        g_drive[(4 * bx + 0) * 512 + tid] = a0;
        g_drive[(4 * bx + 1) * 512 + tid] = a1;
        g_drive[(4 * bx + 2) * 512 + tid] = a2;
        g_drive[(4 * bx + 3) * 512 + tid] = a3;
    }
    grid_barrier(8, 128);   // orders flag resets + ec3 staging vs first polls

    if (tid == 0) {
        int bits = 0;
        for (int i = 0; i < 128; i++) bits |= __ldcg(&g_scan[i]);
        s_mmode = (bits & 1) ? 0 : ((bits & 4) ? 2 : ((bits & 2) ? 1 : 0));
    }
    __syncthreads();
    const int mmode = s_mmode;
    const uint8_t* nm_u8  = (const uint8_t*)noise_mask;
    const int*     nm_i32 = (const int*)noise_mask;
    const float*   nm_f32 = (const float*)noise_mask;

    // ---------------- Load weights + init state ----------------
    for (int idx = tid; idx < 512 * NC; idx += NTHR) {
        int kk = idx >> 5, jj = idx & 31;
        W1s[idx] = wec3ca1[kk * 512 + j0 + jj];
        W2s[idx] = wca1ec5[kk * 512 + j0 + jj];
    }
    const float bias_r = ca1bias[col];
    const float wact0  = wca1act[col * 2];
    const float wact1  = wca1act[col * 2 + 1];
    const float actb0  = actbias[0];
    const float actb1  = actbias[1];
    float ec5v = ec5_last[b * 512 + col];
    float ec3v = ec3_last[b * 512 + col];
    float ca1v = 0.f;
    __syncthreads();

    volatile const unsigned* flagsA = g_flagA + g * CPG;
    volatile const unsigned* flagsB = g_flagB + g * CPG;
    const float* exc3 = g_ex_ec3 + g * RPG * 512;
    const float* exca = g_ex_ca1 + g * RPG * 512;

    // ---------------- Main scan ----------------
    for (int t = 0; t < T; t++) {
        const unsigned tgt = (unsigned)(t + 1);
        const size_t si = (size_t)(b * T + t) * 512 + col;
        float drv = __ldcg(&g_drive[t * 512 + col]);
        float xin = ec3input[si];
        bool  msk = (mmode == 0) ? (nm_u8[si] != 0)
                  : (mmode == 1) ? (nm_i32[si] != 0)
                                 : (nm_f32[si] != 0.0f);

        // ---- Phase A: ca1 = clip(drive * (1 + sigmoid(ec3 @ W1)) - bias) ----
        float z  = gemm_flag(W1s, exc3, flagsB, tgt, x_s, red);
        float sg = __fdividef(1.f, 1.f + __expf(-z));
        ca1v = drv * (1.f + sg) - bias_r;
        ca1v = fminf(fmaxf(ca1v, 0.f), 1.f);
        g_ex_ca1[b * 512 + col] = ca1v;

        // act partials for this CTA's 32 columns (warp reduce)
        {
            float p0 = ca1v * wact0, p1 = ca1v * wact1;
#pragma unroll
            for (int o = 16; o; o >>= 1) {
                p0 += __shfl_down_sync(0xffffffffu, p0, o);
                p1 += __shfl_down_sync(0xffffffffu, p1, o);
            }
            if (lane == 0) {
                float2 pv; pv.x = p0; pv.y = p1;
                *(float2*)&g_ex_act[(b * CPG + ci) * 2] = pv;
            }
        }
        publish(&g_flagA[bx], tgt);
        out[CA1HIS + si] = ca1v;        // off critical path

        // ---- Phase B: ec5/ec3 update ----
        float z2 = gemm_flag(W2s, exca, flagsA, tgt, x_s, red);

        // act finish: warp w handles batch row w (ALL 16 warps, lanes 0-15).
        // Visibility: gemm_flag's 16 per-warp waits + its internal syncthreads
        // imply every flagA >= tgt, so all act partials are in L2.
        if (ci == 0 && lane < 16) {
            float2 actp = __ldcg((const float2*)&g_ex_act[(b * CPG + lane) * 2]);
            float a0 = actp.x, a1 = actp.y;
#pragma unroll
            for (int o = 8; o; o >>= 1) {
                a0 += __shfl_down_sync(0xffffu, a0, o);
                a1 += __shfl_down_sync(0xffffu, a1, o);
            }
            if (lane == 0) {
                out[ACT_OFF + (b * T + t) * 2 + 0] = a0 + actb0;
                out[ACT_OFF + (b * T + t) * 2 + 1] = a1 + actb1;
            }
        }

        float e5 = ec5v + z2;
        e5 = 0.69f + 0.3f * __fdividef(1.f, 1.f + __expf(-4.f * (e5 - 0.3f)));
        float e3 = e5 * ec3v + 0.6f * (1.f - ec3v) * xin;
        if (msk) e3 = 0.5f * e3 + 0.3f;
        ec5v = e5; ec3v = e3;
        g_ex_ec3[b * 512 + col] = e3;
        publish(&g_flagB[bx], tgt + 1u);
        out[EC3HIS + si] = e3;          // off critical path
        out[EC5HIS + si] = e5;
    }

    // ---------------- Finals ----------------
    out[EC3F + b * 512 + col] = ec3v;
    out[EC5F + b * 512 + col] = ec5v;
    out[CA1F + b * 512 + col] = ca1v;
}

extern "C" void kernel_launch(void* const* d_in, const int* in_sizes, int n_in,
                              void* d_out, int out_size) {
    (void)in_sizes; (void)n_in; (void)out_size;
    cudaFuncSetAttribute(rnn_kernel, cudaFuncAttributeMaxDynamicSharedMemorySize,
                         SMEM_BYTES);
    rnn_kernel<<<NGRP * CPG, NTHR, SMEM_BYTES>>>(
        (const float*)d_in[0],      // ec3input
        (const float*)d_in[1],      // ec3_last
        (const float*)d_in[2],      // ec5_last
        (const float*)d_in[3],      // ca1_last (unused)
        (const float*)d_in[4],      // ca1bias
        (const float*)d_in[5],      // wca3ca1
        (const float*)d_in[6],      // wec3ca1
        (const float*)d_in[7],      // wca1ec5
        (const float*)d_in[8],      // wca1act
        (const float*)d_in[9],      // actbias
        d_in[10],                   // noise_mask (encoding auto-detected)
        (const int*)d_in[11],       // ca3order
        (float*)d_out);
}

// round 15
// speedup vs baseline: 1.3411x; 1.3411x over previous
#include <cuda_runtime.h>
#include <cstdint>

#define BS   128
#define T    512
#define E    512
#define NGRP 8          // batch groups
#define RPG  16         // batch rows per group
#define CPG  16         // CTAs per group (column split)
#define NC   32         // output cols per CTA
#define RPAD 516        // padded row stride (floats)
#define NTHR 512

// output layout offsets (float elements)
#define ACT_OFF  0
#define EC3HIS   131072
#define EC5HIS   33685504
#define CA1HIS   67239936
#define EC3F     100794368
#define EC5F     100859904
#define CA1F     100925440

// device scratch
__device__ float    g_drive[T * E];
__device__ float    g_ex_ca1[BS * E];
__device__ float    g_ex_ec3[BS * E];
__device__ float    g_ex_act[BS * CPG * 2];   // per-CTA act partials
__device__ unsigned g_bar_cnt[16];
__device__ unsigned g_bar_gen[16];
__device__ unsigned g_slotA[NGRP * CPG];      // per-CTA monotonic arrival slots
__device__ unsigned g_slotB[NGRP * CPG];
__device__ int      g_scan[128];

// smem layout (floats). The ca1 tile is aliased onto x_s (ec3 elementwise
// state lives in registers, so the x tile is dead after phase-A GEMM reads it).
#define SM_W1    0
#define SM_W2    (512 * NC)                  // 16384
#define SM_X     (2 * 512 * NC)              // 32768
#define SM_RED   (SM_X + RPG * RPAD)         // 41024 (8192 floats = 16 tiles)
#define SM_FLOATS (SM_RED + 8192)            // 49216
#define SMEM_BYTES (SM_FLOATS * 4)           // 196864 B

__device__ __forceinline__ unsigned long long pack2(float x) {
    unsigned long long r;
    asm("mov.b64 %0, {%1, %1};" : "=l"(r) : "f"(x));
    return r;
}
__device__ __forceinline__ void fma2(unsigned long long& d,
                                     unsigned long long a, unsigned long long b) {
    asm("fma.rn.f32x2 %0, %1, %2, %0;" : "+l"(d) : "l"(a), "l"(b));
}

// full-grid sense-reversal barrier (once, after phase 0; 128 CTAs co-resident)
__device__ __forceinline__ void grid_barrier(int idx, unsigned n) {
    __syncthreads();
    if (threadIdx.x == 0) {
        __threadfence();
        volatile unsigned* vgen = g_bar_gen;
        unsigned gen0 = vgen[idx];
        unsigned a = atomicAdd(&g_bar_cnt[idx], 1u);
        if (a == n - 1u) {
            g_bar_cnt[idx] = 0u;
            __threadfence();
            vgen[idx] = gen0 + 1u;
        } else {
            while (vgen[idx] == gen0) { }
        }
        __threadfence();
    }
    __syncthreads();
}

// slot barrier: arrive = single-writer volatile store (no atomic);
// wait = lanes 0-15 poll their own slot (one 64B line, coalesced).
__device__ __forceinline__ void arrive_slot(volatile unsigned* myslot, unsigned val) {
    __syncthreads();                       // all CTA g_ex stores issued
    if (threadIdx.x == 0) {
        __threadfence();                   // make them visible
        *myslot = val;
    }
}
__device__ __forceinline__ void wait_slots(volatile const unsigned* slots,
                                           unsigned target) {
    if (threadIdx.x < CPG) {
        while (slots[threadIdx.x] < target) { }
        __threadfence();
    }
    __syncthreads();
}

// z[16][32] = xs(16 x 512, RPAD stride) @ Ws(512 x 32).
// Warp w owns k-slice [32w,32w+32) of the full 16x32 tile. Lane (rg,cg):
// rows rg+4i, cols 4cg..4cg+3. Single-pass reduction over all 16 tiles.
// NOTE: no leading sync before writing red — the flow guarantees >=3 CTA
// syncs (arrive, wait, gather) between any two invocations.
// Returns z for output (r = tid>>5, j = tid&31) = index tid.
__device__ __forceinline__ float gemm_zval(const float* __restrict__ Ws,
                                           const float* __restrict__ xs,
                                           float* __restrict__ red) {
    const int tid  = threadIdx.x;
    const int warp = tid >> 5, lane = tid & 31;
    const int rg = lane >> 3, cg = lane & 7;

    const float* xb = xs + rg * RPAD + (warp << 5);
    const ulonglong2* wb = (const ulonglong2*)(Ws + (warp << 5) * NC + (cg << 2));

    unsigned long long a00=0ull,a01=0ull,a10=0ull,a11=0ull,
                       a20=0ull,a21=0ull,a30=0ull,a31=0ull;
#pragma unroll
    for (int kb = 0; kb < 32; kb += 4) {
        float4 x0 = *(const float4*)(xb + 0 * 4 * RPAD + kb);
        float4 x1 = *(const float4*)(xb + 1 * 4 * RPAD + kb);
        float4 x2 = *(const float4*)(xb + 2 * 4 * RPAD + kb);
        float4 x3 = *(const float4*)(xb + 3 * 4 * RPAD + kb);
        ulonglong2 w0 = wb[(kb + 0) * 8];
        ulonglong2 w1 = wb[(kb + 1) * 8];
        ulonglong2 w2 = wb[(kb + 2) * 8];
        ulonglong2 w3 = wb[(kb + 3) * 8];
        unsigned long long p;
        p = pack2(x0.x); fma2(a00, p, w0.x); fma2(a01, p, w0.y);
        p = pack2(x0.y); fma2(a00, p, w1.x); fma2(a01, p, w1.y);
        p = pack2(x0.z); fma2(a00, p, w2.x); fma2(a01, p, w2.y);
        p = pack2(x0.w); fma2(a00, p, w3.x); fma2(a01, p, w3.y);
        p = pack2(x1.x); fma2(a10, p, w0.x); fma2(a11, p, w0.y);
        p = pack2(x1.y); fma2(a10, p, w1.x); fma2(a11, p, w1.y);
        p = pack2(x1.z); fma2(a10, p, w2.x); fma2(a11, p, w2.y);
        p = pack2(x1.w); fma2(a10, p, w3.x); fma2(a11, p, w3.y);
        p = pack2(x2.x); fma2(a20, p, w0.x); fma2(a21, p, w0.y);
        p = pack2(x2.y); fma2(a20, p, w1.x); fma2(a21, p, w1.y);
        p = pack2(x2.z); fma2(a20, p, w2.x); fma2(a21, p, w2.y);
        p = pack2(x2.w); fma2(a20, p, w3.x); fma2(a21, p, w3.y);
        p = pack2(x3.x); fma2(a30, p, w0.x); fma2(a31, p, w0.y);
        p = pack2(x3.y); fma2(a30, p, w1.x); fma2(a31, p, w1.y);
        p = pack2(x3.z); fma2(a30, p, w2.x); fma2(a31, p, w2.y);
        p = pack2(x3.w); fma2(a30, p, w3.x); fma2(a31, p, w3.y);
    }

    unsigned long long* buf64 = (unsigned long long*)red;
    {
        unsigned long long* d = buf64 + (warp << 8) + rg * 16 + cg * 2;
        ulonglong2 v;
        v.x = a00; v.y = a01; *(ulonglong2*)(d)       = v;
        v.x = a10; v.y = a11; *(ulonglong2*)(d + 64)  = v;
        v.x = a20; v.y = a21; *(ulonglong2*)(d + 128) = v;
        v.x = a30; v.y = a31; *(ulonglong2*)(d + 192) = v;
    }
    __syncthreads();
    const int o = tid;
    float s0 = red[o]        + red[512  + o];
    float s1 = red[1024 + o] + red[1536 + o];
    float s2 = red[2048 + o] + red[2560 + o];
    float s3 = red[3072 + o] + red[3584 + o];
    float s4 = red[4096 + o] + red[4608 + o];
    float s5 = red[5120 + o] + red[5632 + o];
    float s6 = red[6144 + o] + red[6656 + o];
    float s7 = red[7168 + o] + red[7680 + o];
    return ((s0 + s1) + (s2 + s3)) + ((s4 + s5) + (s6 + s7));
}

__global__ void __launch_bounds__(NTHR, 1)
rnn_kernel(const float* __restrict__ ec3input,
           const float* __restrict__ ec3_last,
           const float* __restrict__ ec5_last,
           const float* __restrict__ ca1_last,
           const float* __restrict__ ca1bias,
           const float* __restrict__ wca3ca1,
           const float* __restrict__ wec3ca1,
           const float* __restrict__ wca1ec5,
           const float* __restrict__ wca1act,
           const float* __restrict__ actbias,
           const void* __restrict__ noise_mask,
           const int* __restrict__ ca3order,
           float* __restrict__ out) {
    extern __shared__ float smem[];
    float* W1s = smem + SM_W1;
    float* W2s = smem + SM_W2;
    float* x_s = smem + SM_X;     // ec3 tile, then (aliased) ca1 tile
    float* red = smem + SM_RED;
    __shared__ int s_mmode;

    const int tid = threadIdx.x;
    const int bx  = blockIdx.x;
    const int g   = bx >> 4;
    const int ci  = bx & 15;
    const int j0  = ci * NC;
    const int r   = tid >> 5;        // row 0..15
    const int j   = tid & 31;
    const int lane = tid & 31;
    const int b   = g * RPG + r;
    const int col = j0 + j;

    // reset this CTA's slots (ordered by the grid barrier below)
    if (tid == 0) { g_slotA[bx] = 0u; g_slotB[bx] = 0u; }

    // ---------------- Phase 0a: mask-dtype scan ----------------
    if (tid == 0) g_scan[bx] = 0;
    __syncthreads();
    {
        const uint4* mw = (const uint4*)noise_mask;
        int bits = 0;
#pragma unroll
        for (int u = 0; u < 16; u++) {
            uint4 w = __ldcg(&mw[(size_t)bx * 8192 + (size_t)u * 512 + tid]);
            unsigned ws[4] = {w.x, w.y, w.z, w.w};
#pragma unroll
            for (int e = 0; e < 4; e++) {
                unsigned v = ws[e];
                if (v) {
                    if (v == 1u)               bits |= 2;
                    else if (v == 0x3F800000u) bits |= 4;
                    else                       bits |= 1;
                }
            }
        }
        if (bits) atomicOr(&g_scan[bx], bits);
    }

    // ---------------- Phase 0b: ca3drive precompute ----------------
    {
        float* ca3v = red;               // scratch (2048 of 8192 floats)
        const float stepv = 614.4f / 511.0f;
        const int   ordc  = ca3order[tid];
        const float cen   = -51.2f + stepv * (float)ordc;
#pragma unroll
        for (int i = 0; i < 4; i++) {
            float d = cen - (float)(4 * bx + i);
            ca3v[i * 512 + tid] = expf(-d * d * 0.02f);
        }
        __syncthreads();
        float a0 = 0.f, a1 = 0.f, a2 = 0.f, a3 = 0.f;
#pragma unroll 4
        for (int c = 0; c < 512; c++) {
            float wv = wca3ca1[c * 512 + tid];
            a0 = fmaf(ca3v[c],        wv, a0);
            a1 = fmaf(ca3v[512 + c],  wv, a1);
            a2 = fmaf(ca3v[1024 + c], wv, a2);
            a3 = fmaf(ca3v[1536 + c], wv, a3);
        }
        g_drive[(4 * bx + 0) * 512 + tid] = a0;
        g_drive[(4 * bx + 1) * 512 + tid] = a1;
        g_drive[(4 * bx + 2) * 512 + tid] = a2;
        g_drive[(4 * bx + 3) * 512 + tid] = a3;
    }
    grid_barrier(8, 128);

    if (tid == 0) {
        int bits = 0;
        for (int i = 0; i < 128; i++) bits |= __ldcg(&g_scan[i]);
        s_mmode = (bits & 1) ? 0 : ((bits & 4) ? 2 : ((bits & 2) ? 1 : 0));
    }
    __syncthreads();
    const int mmode = s_mmode;
    const uint8_t* nm_u8  = (const uint8_t*)noise_mask;
    const int*     nm_i32 = (const int*)noise_mask;
    const float*   nm_f32 = (const float*)noise_mask;

    // ---------------- Load weights + init state ----------------
    for (int idx = tid; idx < 512 * NC; idx += NTHR) {
        int kk = idx >> 5, jj = idx & 31;
        W1s[idx] = wec3ca1[kk * 512 + j0 + jj];
        W2s[idx] = wca1ec5[kk * 512 + j0 + jj];
    }
    const float bias_r = ca1bias[col];
    const float wact0  = wca1act[col * 2];
    const float wact1  = wca1act[col * 2 + 1];
    const float actb0  = actbias[0];
    const float actb1  = actbias[1];
    for (int u = tid; u < RPG * 128; u += NTHR) {
        int rr = u >> 7, kk = (u & 127) << 2;
        *(float4*)(x_s + rr * RPAD + kk) =
            *(const float4*)(ec3_last + (g * RPG + rr) * 512 + kk);
    }
    float ec5v = ec5_last[b * 512 + col];
    float ec3v = ec3_last[b * 512 + col];
    float ca1v = 0.f;
    __syncthreads();

    volatile const unsigned* slotsA = g_slotA + g * CPG;
    volatile const unsigned* slotsB = g_slotB + g * CPG;

    // ---------------- Main scan ----------------
    for (int t = 0; t < T; t++) {
        const unsigned tgt = (unsigned)(t + 1);
        const size_t si = (size_t)(b * T + t) * 512 + col;
        float drv = __ldcg(&g_drive[t * 512 + col]);
        float xin = ec3input[si];
        bool  msk = (mmode == 0) ? (nm_u8[si] != 0)
                  : (mmode == 1) ? (nm_i32[si] != 0)
                                 : (nm_f32[si] != 0.0f);

        // ---- Phase A: ca1 = clip(drive * (1 + sigmoid(ec3 @ W1)) - bias) ----
        float z  = gemm_zval(W1s, x_s, red);
        float sg = __fdividef(1.f, 1.f + __expf(-z));
        ca1v = drv * (1.f + sg) - bias_r;
        ca1v = fminf(fmaxf(ca1v, 0.f), 1.f);
        g_ex_ca1[b * 512 + col] = ca1v;

        // act partials for this CTA's 32 columns (warp reduce)
        {
            float p0 = ca1v * wact0, p1 = ca1v * wact1;
#pragma unroll
            for (int o = 16; o; o >>= 1) {
                p0 += __shfl_down_sync(0xffffffffu, p0, o);
                p1 += __shfl_down_sync(0xffffffffu, p1, o);
            }
            if (lane == 0) {
                float2 pv; pv.x = p0; pv.y = p1;
                *(float2*)&g_ex_act[(b * CPG + ci) * 2] = pv;
            }
        }
        arrive_slot(&g_slotA[bx], tgt);
        out[CA1HIS + si] = ca1v;        // hidden in arrive->wait gap
        wait_slots(slotsA, tgt);

        // act partial prefetch (ci 0 finishes act under the gather)
        float2 actp; actp.x = 0.f; actp.y = 0.f;
        if (ci == 0 && lane < 16)
            actp = __ldcg((const float2*)&g_ex_act[(b * CPG + lane) * 2]);

        // gather full ca1 rows into x_s (aliased; ec3 tile is dead)
#pragma unroll
        for (int u = tid; u < RPG * 128; u += NTHR) {
            int rr = u >> 7, kk = (u & 127) << 2;
            *(float4*)(x_s + rr * RPAD + kk) =
                __ldcg((const float4*)(g_ex_ca1 + (g * RPG + rr) * 512 + kk));
        }
        __syncthreads();

        if (ci == 0 && lane < 16) {
            float a0 = actp.x, a1 = actp.y;
#pragma unroll
            for (int o = 8; o; o >>= 1) {
                a0 += __shfl_down_sync(0xffffu, a0, o);
                a1 += __shfl_down_sync(0xffffu, a1, o);
            }
            if (lane == 0) {
                out[ACT_OFF + (b * T + t) * 2 + 0] = a0 + actb0;
                out[ACT_OFF + (b * T + t) * 2 + 1] = a1 + actb1;
            }
        }

        // ---- Phase B: ec5/ec3 update ----
        float z2 = gemm_zval(W2s, x_s, red);
        float e5 = ec5v + z2;
        e5 = 0.69f + 0.3f * __fdividef(1.f, 1.f + __expf(-4.f * (e5 - 0.3f)));
        float e3 = e5 * ec3v + 0.6f * (1.f - ec3v) * xin;
        if (msk) e3 = 0.5f * e3 + 0.3f;
        ec5v = e5; ec3v = e3;
        g_ex_ec3[b * 512 + col] = e3;
        arrive_slot(&g_slotB[bx], tgt);
        out[EC3HIS + si] = e3;          // hidden in arrive->wait gap
        out[EC5HIS + si] = e5;

        if (t + 1 < T) {                // final step: no more consumers
            wait_slots(slotsB, tgt);
            // gather full new ec3 rows into x_s
#pragma unroll
            for (int u = tid; u < RPG * 128; u += NTHR) {
                int rr = u >> 7, kk = (u & 127) << 2;
                *(float4*)(x_s + rr * RPAD + kk) =
                    __ldcg((const float4*)(g_ex_ec3 + (g * RPG + rr) * 512 + kk));
            }
            __syncthreads();
        }
    }

    // ---------------- Finals ----------------
    out[EC3F + b * 512 + col] = ec3v;
    out[EC5F + b * 512 + col] = ec5v;
    out[CA1F + b * 512 + col] = ca1v;
}

extern "C" void kernel_launch(void* const* d_in, const int* in_sizes, int n_in,
                              void* d_out, int out_size) {
    (void)in_sizes; (void)n_in; (void)out_size;
    cudaFuncSetAttribute(rnn_kernel, cudaFuncAttributeMaxDynamicSharedMemorySize,
                         SMEM_BYTES);
    rnn_kernel<<<NGRP * CPG, NTHR, SMEM_BYTES>>>(
        (const float*)d_in[0],      // ec3input
        (const float*)d_in[1],      // ec3_last
        (const float*)d_in[2],      // ec5_last
        (const float*)d_in[3],      // ca1_last (unused)
        (const float*)d_in[4],      // ca1bias
        (const float*)d_in[5],      // wca3ca1
        (const float*)d_in[6],      // wec3ca1
        (const float*)d_in[7],      // wca1ec5
        (const float*)d_in[8],      // wca1act
        (const float*)d_in[9],      // actbias
        d_in[10],                   // noise_mask (encoding auto-detected)
        (const int*)d_in[11],       // ca3order
        (float*)d_out);
}

// round 16
// speedup vs baseline: 1.7461x; 1.3019x over previous
#include <cuda_runtime.h>
#include <cstdint>

#define BS   128
#define T    512
#define E    512
#define NGRP 8          // batch groups
#define RPG  16         // batch rows per group
#define CPG  32         // CTAs per group (column split)
#define NC   16         // output cols per CTA
#define RPAD 516        // padded row stride (floats)
#define NTHR 256
#define NCTA (NGRP * CPG)   // 256

// output layout offsets (float elements)
#define ACT_OFF  0
#define EC3HIS   131072
#define EC5HIS   33685504
#define CA1HIS   67239936
#define EC3F     100794368
#define EC5F     100859904
#define CA1F     100925440

// device scratch
__device__ float    g_drive[T * E];
__device__ float    g_ex_ca1[BS * E];
__device__ float    g_ex_ec3[BS * E];
__device__ float    g_ex_act[BS * CPG * 2];   // per-CTA act partials
__device__ unsigned g_bar_cnt[16];
__device__ unsigned g_bar_gen[16];
__device__ unsigned g_pcnt[NGRP * 2];         // monotonic counters (A, B per group)
__device__ int      g_scan[NCTA];

// smem layout (floats); ~104 KB total -> 2 CTAs per SM
#define SM_W1    0
#define SM_W2    (512 * NC)                  // 8192
#define SM_X     (2 * 512 * NC)              // 16384
#define SM_RED   (SM_X + RPG * RPAD)         // 24640 (2048 floats = 8 tiles)
#define SM_FLOATS (SM_RED + 2048)            // 26688
#define SMEM_BYTES (SM_FLOATS * 4)           // 106752 B

__device__ __forceinline__ unsigned long long pack2(float x) {
    unsigned long long r;
    asm("mov.b64 %0, {%1, %1};" : "=l"(r) : "f"(x));
    return r;
}
__device__ __forceinline__ void fma2(unsigned long long& d,
                                     unsigned long long a, unsigned long long b) {
    asm("fma.rn.f32x2 %0, %1, %2, %0;" : "+l"(d) : "l"(a), "l"(b));
}

// full-grid sense-reversal barrier (once, after phase 0).
// 256 CTAs, 2/SM occupancy -> capacity 296 >= 256: all co-resident.
__device__ __forceinline__ void grid_barrier(int idx, unsigned n) {
    __syncthreads();
    if (threadIdx.x == 0) {
        __threadfence();
        volatile unsigned* vgen = g_bar_gen;
        unsigned gen0 = vgen[idx];
        unsigned a = atomicAdd(&g_bar_cnt[idx], 1u);
        if (a == n - 1u) {
            g_bar_cnt[idx] = 0u;
            __threadfence();
            vgen[idx] = gen0 + 1u;
        } else {
            while (vgen[idx] == gen0) { }
        }
        __threadfence();
    }
    __syncthreads();
}

// split arrive / wait on monotonic per-group counters (tid0-only poll)
__device__ __forceinline__ void p_arrive(int slot) {
    __syncthreads();                       // all CTA g_ex stores issued
    if (threadIdx.x == 0) {
        __threadfence();                   // make them visible
        atomicAdd(&g_pcnt[slot], 1u);
    }
}
__device__ __forceinline__ void p_wait(int slot, unsigned target) {
    if (threadIdx.x == 0) {
        volatile unsigned* c = g_pcnt;
        while (c[slot] < target) { }
        __threadfence();
    }
    __syncthreads();
}

// z[16][16] = xs(16 x 512, RPAD stride) @ Ws(512 x 16).
// 8 warps; warp w owns k-slice [64w, 64w+64). Lane (rg = lane>>2 in 0..7,
// cg = lane&3 in 0..3): rows rg, rg+8; cols 4cg..4cg+3 (2 f32x2 accs/row).
// Single-pass reduction over the 8 partial tiles (256 floats each).
// Returns z for output index tid (r = tid>>4, j = tid&15).
__device__ __forceinline__ float gemm_zval(const float* __restrict__ Ws,
                                           const float* __restrict__ xs,
                                           float* __restrict__ red) {
    const int tid  = threadIdx.x;
    const int warp = tid >> 5, lane = tid & 31;
    const int rg = lane >> 2, cg = lane & 3;

    const float* xb = xs + rg * RPAD + (warp << 6);
    // row k of W is 16 floats = 4 ulonglong2; lane reads the cg-th 16B chunk
    const ulonglong2* wb = (const ulonglong2*)Ws + ((warp << 6) << 2) + cg;

    unsigned long long a00 = 0ull, a01 = 0ull, a10 = 0ull, a11 = 0ull;
#pragma unroll
    for (int kb = 0; kb < 64; kb += 4) {
        float4 x0 = *(const float4*)(xb + kb);              // row rg
        float4 x1 = *(const float4*)(xb + 8 * RPAD + kb);   // row rg+8
        ulonglong2 w0 = wb[(kb + 0) << 2];
        ulonglong2 w1 = wb[(kb + 1) << 2];
        ulonglong2 w2 = wb[(kb + 2) << 2];
        ulonglong2 w3 = wb[(kb + 3) << 2];
        unsigned long long p;
        p = pack2(x0.x); fma2(a00, p, w0.x); fma2(a01, p, w0.y);
        p = pack2(x0.y); fma2(a00, p, w1.x); fma2(a01, p, w1.y);
        p = pack2(x0.z); fma2(a00, p, w2.x); fma2(a01, p, w2.y);
        p = pack2(x0.w); fma2(a00, p, w3.x); fma2(a01, p, w3.y);
        p = pack2(x1.x); fma2(a10, p, w0.x); fma2(a11, p, w0.y);
        p = pack2(x1.y); fma2(a10, p, w1.x); fma2(a11, p, w1.y);
        p = pack2(x1.z); fma2(a10, p, w2.x); fma2(a11, p, w2.y);
        p = pack2(x1.w); fma2(a10, p, w3.x); fma2(a11, p, w3.y);
    }

    // partial tile write: tile w = 256 floats = 128 u64; row stride 8 u64
    unsigned long long* buf64 = (unsigned long long*)red;
    {
        unsigned long long* d = buf64 + (warp << 7) + rg * 8 + cg * 2;
        ulonglong2 v;
        v.x = a00; v.y = a01; *(ulonglong2*)(d)      = v;   // row rg
        v.x = a10; v.y = a11; *(ulonglong2*)(d + 64) = v;   // row rg+8
    }
    __syncthreads();
    const int o = tid;
    float s0 = red[o]        + red[256  + o];
    float s1 = red[512  + o] + red[768  + o];
    float s2 = red[1024 + o] + red[1280 + o];
    float s3 = red[1536 + o] + red[1792 + o];
    return (s0 + s1) + (s2 + s3);
}

__global__ void __launch_bounds__(NTHR, 2)
rnn_kernel(const float* __restrict__ ec3input,
           const float* __restrict__ ec3_last,
           const float* __restrict__ ec5_last,
           const float* __restrict__ ca1_last,
           const float* __restrict__ ca1bias,
           const float* __restrict__ wca3ca1,
           const float* __restrict__ wec3ca1,
           const float* __restrict__ wca1ec5,
           const float* __restrict__ wca1act,
           const float* __restrict__ actbias,
           const void* __restrict__ noise_mask,
           const int* __restrict__ ca3order,
           float* __restrict__ out) {
    extern __shared__ float smem[];
    float* W1s = smem + SM_W1;
    float* W2s = smem + SM_W2;
    float* x_s = smem + SM_X;     // ec3 tile, then (aliased) ca1 tile
    float* red = smem + SM_RED;
    __shared__ int s_mmode;

    const int tid = threadIdx.x;
    const int bx  = blockIdx.x;
    const int g   = bx >> 5;         // batch group (0..7)
    const int ci  = bx & 31;         // column CTA (0..31)
    const int j0  = ci * NC;
    const int r   = tid >> 4;        // row 0..15
    const int j   = tid & 15;
    const int lane = tid & 31;
    const int b   = g * RPG + r;
    const int col = j0 + j;

    // reset this group's phase counters (ordered by the grid barrier below)
    if (ci == 0 && tid < 2) g_pcnt[g * 2 + tid] = 0u;

    // ---------------- Phase 0a: mask-dtype scan ----------------
    if (tid == 0) g_scan[bx] = 0;
    __syncthreads();
    {
        const uint4* mw = (const uint4*)noise_mask;
        int bits = 0;
#pragma unroll
        for (int u = 0; u < 4; u++) {
            uint4 w = __ldcg(&mw[(size_t)bx * 4096 + (size_t)u * 1024 + tid]);
            unsigned ws[4] = {w.x, w.y, w.z, w.w};
#pragma unroll
            for (int e = 0; e < 4; e++) {
                unsigned v = ws[e];
                if (v) {
                    if (v == 1u)               bits |= 2;
                    else if (v == 0x3F800000u) bits |= 4;
                    else                       bits |= 1;
                }
            }
        }
        if (bits) atomicOr(&g_scan[bx], bits);
    }

    // ---------------- Phase 0b: ca3drive precompute ----------------
    // CTA bx computes drive rows t = 2*bx, 2*bx+1 (all 512 cols).
    {
        float* ca3v = red;               // scratch: 1024 of 2048 floats
        const float stepv = 614.4f / 511.0f;
        const int   ord0  = ca3order[tid];
        const int   ord1  = ca3order[tid + 256];
        const float cen0  = -51.2f + stepv * (float)ord0;
        const float cen1  = -51.2f + stepv * (float)ord1;
#pragma unroll
        for (int i = 0; i < 2; i++) {
            float d0 = cen0 - (float)(2 * bx + i);
            float d1 = cen1 - (float)(2 * bx + i);
            ca3v[i * 512 + tid]       = expf(-d0 * d0 * 0.02f);
            ca3v[i * 512 + tid + 256] = expf(-d1 * d1 * 0.02f);
        }
        __syncthreads();
        float a00 = 0.f, a01 = 0.f, a10 = 0.f, a11 = 0.f;
#pragma unroll 4
        for (int c = 0; c < 512; c++) {
            float wv0 = wca3ca1[c * 512 + tid];
            float wv1 = wca3ca1[c * 512 + tid + 256];
            a00 = fmaf(ca3v[c],       wv0, a00);
            a01 = fmaf(ca3v[c],       wv1, a01);
            a10 = fmaf(ca3v[512 + c], wv0, a10);
            a11 = fmaf(ca3v[512 + c], wv1, a11);
        }
        g_drive[(2 * bx + 0) * 512 + tid]       = a00;
        g_drive[(2 * bx + 0) * 512 + tid + 256] = a01;
        g_drive[(2 * bx + 1) * 512 + tid]       = a10;
        g_drive[(2 * bx + 1) * 512 + tid + 256] = a11;
    }
    grid_barrier(8, NCTA);

    if (tid == 0) {
        int bits = 0;
        for (int i = 0; i < NCTA; i++) bits |= __ldcg(&g_scan[i]);
        s_mmode = (bits & 1) ? 0 : ((bits & 4) ? 2 : ((bits & 2) ? 1 : 0));
    }
    __syncthreads();
    const int mmode = s_mmode;
    const uint8_t* nm_u8  = (const uint8_t*)noise_mask;
    const int*     nm_i32 = (const int*)noise_mask;
    const float*   nm_f32 = (const float*)noise_mask;

    // ---------------- Load weights + init state ----------------
    for (int idx = tid; idx < 512 * NC; idx += NTHR) {
        int kk = idx >> 4, jj = idx & 15;
        W1s[idx] = wec3ca1[kk * 512 + j0 + jj];
        W2s[idx] = wca1ec5[kk * 512 + j0 + jj];
    }
    const float bias_r = ca1bias[col];
    const float wact0  = wca1act[col * 2];
    const float wact1  = wca1act[col * 2 + 1];
    const float actb0  = actbias[0];
    const float actb1  = actbias[1];
    for (int u = tid; u < RPG * 128; u += NTHR) {
        int rr = u >> 7, kk = (u & 127) << 2;
        *(float4*)(x_s + rr * RPAD + kk) =
            *(const float4*)(ec3_last + (g * RPG + rr) * 512 + kk);
    }
    float ec5v = ec5_last[b * 512 + col];
    float ec3v = ec3_last[b * 512 + col];
    float ca1v = 0.f;
    __syncthreads();

    const int slotA = g * 2, slotB = g * 2 + 1;

    // ---------------- Main scan ----------------
    for (int t = 0; t < T; t++) {
        const unsigned tgt = (unsigned)(CPG * (t + 1));
        const size_t si = (size_t)(b * T + t) * 512 + col;
        float drv = __ldcg(&g_drive[t * 512 + col]);
        float xin = ec3input[si];
        bool  msk = (mmode == 0) ? (nm_u8[si] != 0)
                  : (mmode == 1) ? (nm_i32[si] != 0)
                                 : (nm_f32[si] != 0.0f);

        // ---- Phase A: ca1 = clip(drive * (1 + sigmoid(ec3 @ W1)) - bias) ----
        float z  = gemm_zval(W1s, x_s, red);
        float sg = __fdividef(1.f, 1.f + __expf(-z));
        ca1v = drv * (1.f + sg) - bias_r;
        ca1v = fminf(fmaxf(ca1v, 0.f), 1.f);
        g_ex_ca1[b * 512 + col] = ca1v;

        // act partials for this CTA's 16 columns (half-warp reduce; warp w
        // covers rows 2w (lanes 0-15) and 2w+1 (lanes 16-31))
        {
            float p0 = ca1v * wact0, p1 = ca1v * wact1;
#pragma unroll
            for (int o = 8; o; o >>= 1) {
                p0 += __shfl_down_sync(0xffffffffu, p0, o, 16);
                p1 += __shfl_down_sync(0xffffffffu, p1, o, 16);
            }
            if ((lane & 15) == 0) {
                float2 pv; pv.x = p0; pv.y = p1;
                *(float2*)&g_ex_act[(b * CPG + ci) * 2] = pv;
            }
        }
        p_arrive(slotA);
        out[CA1HIS + si] = ca1v;        // hidden in arrive->wait gap
        p_wait(slotA, tgt);

        // gather full ca1 rows into x_s (aliased; ec3 tile is dead)
#pragma unroll
        for (int u = tid; u < RPG * 128; u += NTHR) {
            int rr = u >> 7, kk = (u & 127) << 2;
            *(float4*)(x_s + rr * RPAD + kk) =
                __ldcg((const float4*)(g_ex_ca1 + (g * RPG + rr) * 512 + kk));
        }
        __syncthreads();

        // act finish: warp w reduces rows 2w and 2w+1 (32 partials each)
        if (ci == 0) {
            const int row0 = (tid >> 5) * 2;
#pragma unroll
            for (int rr = 0; rr < 2; rr++) {
                int bb = g * RPG + row0 + rr;
                float2 actp = __ldcg((const float2*)&g_ex_act[(bb * CPG + lane) * 2]);
                float a0 = actp.x, a1 = actp.y;
#pragma unroll
                for (int o = 16; o; o >>= 1) {
                    a0 += __shfl_down_sync(0xffffffffu, a0, o);
                    a1 += __shfl_down_sync(0xffffffffu, a1, o);
                }
                if (lane == 0) {
                    out[ACT_OFF + (bb * T + t) * 2 + 0] = a0 + actb0;
                    out[ACT_OFF + (bb * T + t) * 2 + 1] = a1 + actb1;
                }
            }
        }

        // ---- Phase B: ec5/ec3 update ----
        float z2 = gemm_zval(W2s, x_s, red);
        float e5 = ec5v + z2;
        e5 = 0.69f + 0.3f * __fdividef(1.f, 1.f + __expf(-4.f * (e5 - 0.3f)));
        float e3 = e5 * ec3v + 0.6f * (1.f - ec3v) * xin;
        if (msk) e3 = 0.5f * e3 + 0.3f;
        ec5v = e5; ec3v = e3;
        g_ex_ec3[b * 512 + col] = e3;
        p_arrive(slotB);
        out[EC3HIS + si] = e3;          // hidden in arrive->wait gap
        out[EC5HIS + si] = e5;

        if (t + 1 < T) {                // final step: no more consumers
            p_wait(slotB, tgt);
            // gather full new ec3 rows into x_s
#pragma unroll
            for (int u = tid; u < RPG * 128; u += NTHR) {
                int rr = u >> 7, kk = (u & 127) << 2;
                *(float4*)(x_s + rr * RPAD + kk) =
                    __ldcg((const float4*)(g_ex_ec3 + (g * RPG + rr) * 512 + kk));
            }
            __syncthreads();
        }
    }

    // ---------------- Finals ----------------
    out[EC3F + b * 512 + col] = ec3v;
    out[EC5F + b * 512 + col] = ec5v;
    out[CA1F + b * 512 + col] = ca1v;
}

extern "C" void kernel_launch(void* const* d_in, const int* in_sizes, int n_in,
                              void* d_out, int out_size) {
    (void)in_sizes; (void)n_in; (void)out_size;
    cudaFuncSetAttribute(rnn_kernel, cudaFuncAttributeMaxDynamicSharedMemorySize,
                         SMEM_BYTES);
    rnn_kernel<<<NCTA, NTHR, SMEM_BYTES>>>(
        (const float*)d_in[0],      // ec3input
        (const float*)d_in[1],      // ec3_last
        (const float*)d_in[2],      // ec5_last
        (const float*)d_in[3],      // ca1_last (unused)
        (const float*)d_in[4],      // ca1bias
        (const float*)d_in[5],      // wca3ca1
        (const float*)d_in[6],      // wec3ca1
        (const float*)d_in[7],      // wca1ec5
        (const float*)d_in[8],      // wca1act
        (const float*)d_in[9],      // actbias
        d_in[10],                   // noise_mask (encoding auto-detected)
        (const int*)d_in[11],       // ca3order
        (float*)d_out);
}

// round 17
// speedup vs baseline: 2.2370x; 1.2812x over previous
#include <cuda_runtime.h>
#include <cstdint>

#define BS   128
#define T    512
#define E    512
#define NGRP 8          // batch groups
#define RPG  16         // batch rows per group
#define CPG  16         // CTAs per group (column split)
#define NC   32         // output cols per CTA
#define RPAD 516        // padded row stride (floats)
#define NTHR 512

// output layout offsets (float elements)
#define ACT_OFF  0
#define EC3HIS   131072
#define EC5HIS   33685504
#define CA1HIS   67239936
#define EC3F     100794368
#define EC5F     100859904
#define CA1F     100925440

// device scratch
__device__ float    g_drive[T * E];
__device__ float    g_ex_ca1[BS * E];
__device__ float    g_ex_ec3[BS * E];
__device__ float    g_ex_act[BS * CPG * 2];   // per-CTA act partials
__device__ unsigned g_bar_cnt[16];
__device__ unsigned g_bar_gen[16];
__device__ unsigned g_pcnt[NGRP * 2];         // monotonic counters (A, B per group)
__device__ int      g_scan[128];

// smem layout (floats). The ca1 tile is aliased onto x_s (ec3 elementwise
// state lives in registers, so the x tile is dead after phase-A GEMM reads it).
#define SM_W1    0
#define SM_W2    (512 * NC)                  // 16384
#define SM_X     (2 * 512 * NC)              // 32768
#define SM_RED   (SM_X + RPG * RPAD)         // 41024 (8192 floats = 16 tiles)
#define SM_FLOATS (SM_RED + 8192)            // 49216
#define SMEM_BYTES (SM_FLOATS * 4)           // 196864 B

__device__ __forceinline__ unsigned long long pack2(float x) {
    unsigned long long r;
    asm("mov.b64 %0, {%1, %1};" : "=l"(r) : "f"(x));
    return r;
}
__device__ __forceinline__ void fma2(unsigned long long& d,
                                     unsigned long long a, unsigned long long b) {
    asm("fma.rn.f32x2 %0, %1, %2, %0;" : "+l"(d) : "l"(a), "l"(b));
}

// full-grid sense-reversal barrier (once, after phase 0; 128 CTAs co-resident)
__device__ __forceinline__ void grid_barrier(int idx, unsigned n) {
    __syncthreads();
    if (threadIdx.x == 0) {
        __threadfence();
        volatile unsigned* vgen = g_bar_gen;
        unsigned gen0 = vgen[idx];
        unsigned a = atomicAdd(&g_bar_cnt[idx], 1u);
        if (a == n - 1u) {
            g_bar_cnt[idx] = 0u;
            __threadfence();
            vgen[idx] = gen0 + 1u;
        } else {
            while (vgen[idx] == gen0) { }
        }
        __threadfence();
    }
    __syncthreads();
}

// split arrive / wait on monotonic per-group counters (tid0-only poll)
__device__ __forceinline__ void p_arrive(int slot) {
    __syncthreads();                       // all CTA g_ex stores issued
    if (threadIdx.x == 0) {
        __threadfence();                   // make them visible
        atomicAdd(&g_pcnt[slot], 1u);
    }
}
__device__ __forceinline__ void p_wait(int slot, unsigned target) {
    if (threadIdx.x == 0) {
        volatile unsigned* c = g_pcnt;
        while (c[slot] < target) { }
        __threadfence();
    }
    __syncthreads();
}

// z[16][32] = xs(16 x 512, RPAD stride) @ Ws(512 x 32).
// Warp w owns k-slice [32w,32w+32) of the full 16x32 tile. Lane (rg,cg):
// rows rg+4i, cols 4cg..4cg+3. Single-pass reduction over all 16 tiles.
// NOTE: no leading sync before writing red — the flow guarantees >=3 CTA
// syncs (arrive, wait, gather) between any two invocations.
// Returns z for output (r = tid>>5, j = tid&31) = index tid.
__device__ __forceinline__ float gemm_zval(const float* __restrict__ Ws,
                                           const float* __restrict__ xs,
                                           float* __restrict__ red) {
    const int tid  = threadIdx.x;
    const int warp = tid >> 5, lane = tid & 31;
    const int rg = lane >> 3, cg = lane & 7;

    const float* xb = xs + rg * RPAD + (warp << 5);
    const ulonglong2* wb = (const ulonglong2*)(Ws + (warp << 5) * NC + (cg << 2));

    unsigned long long a00=0ull,a01=0ull,a10=0ull,a11=0ull,
                       a20=0ull,a21=0ull,a30=0ull,a31=0ull;
#pragma unroll
    for (int kb = 0; kb < 32; kb += 4) {
        float4 x0 = *(const float4*)(xb + 0 * 4 * RPAD + kb);
        float4 x1 = *(const float4*)(xb + 1 * 4 * RPAD + kb);
        float4 x2 = *(const float4*)(xb + 2 * 4 * RPAD + kb);
        float4 x3 = *(const float4*)(xb + 3 * 4 * RPAD + kb);
        ulonglong2 w0 = wb[(kb + 0) * 8];
        ulonglong2 w1 = wb[(kb + 1) * 8];
        ulonglong2 w2 = wb[(kb + 2) * 8];
        ulonglong2 w3 = wb[(kb + 3) * 8];
        unsigned long long p;
        p = pack2(x0.x); fma2(a00, p, w0.x); fma2(a01, p, w0.y);
        p = pack2(x0.y); fma2(a00, p, w1.x); fma2(a01, p, w1.y);
        p = pack2(x0.z); fma2(a00, p, w2.x); fma2(a01, p, w2.y);
        p = pack2(x0.w); fma2(a00, p, w3.x); fma2(a01, p, w3.y);
        p = pack2(x1.x); fma2(a10, p, w0.x); fma2(a11, p, w0.y);
        p = pack2(x1.y); fma2(a10, p, w1.x); fma2(a11, p, w1.y);
        p = pack2(x1.z); fma2(a10, p, w2.x); fma2(a11, p, w2.y);
        p = pack2(x1.w); fma2(a10, p, w3.x); fma2(a11, p, w3.y);
        p = pack2(x2.x); fma2(a20, p, w0.x); fma2(a21, p, w0.y);
        p = pack2(x2.y); fma2(a20, p, w1.x); fma2(a21, p, w1.y);
        p = pack2(x2.z); fma2(a20, p, w2.x); fma2(a21, p, w2.y);
        p = pack2(x2.w); fma2(a20, p, w3.x); fma2(a21, p, w3.y);
        p = pack2(x3.x); fma2(a30, p, w0.x); fma2(a31, p, w0.y);
        p = pack2(x3.y); fma2(a30, p, w1.x); fma2(a31, p, w1.y);
        p = pack2(x3.z); fma2(a30, p, w2.x); fma2(a31, p, w2.y);
        p = pack2(x3.w); fma2(a30, p, w3.x); fma2(a31, p, w3.y);
    }

    unsigned long long* buf64 = (unsigned long long*)red;
    {
        unsigned long long* d = buf64 + (warp << 8) + rg * 16 + cg * 2;
        ulonglong2 v;
        v.x = a00; v.y = a01; *(ulonglong2*)(d)       = v;
        v.x = a10; v.y = a11; *(ulonglong2*)(d + 64)  = v;
        v.x = a20; v.y = a21; *(ulonglong2*)(d + 128) = v;
        v.x = a30; v.y = a31; *(ulonglong2*)(d + 192) = v;
    }
    __syncthreads();
    const int o = tid;
    float s0 = red[o]        + red[512  + o];
    float s1 = red[1024 + o] + red[1536 + o];
    float s2 = red[2048 + o] + red[2560 + o];
    float s3 = red[3072 + o] + red[3584 + o];
    float s4 = red[4096 + o] + red[4608 + o];
    float s5 = red[5120 + o] + red[5632 + o];
    float s6 = red[6144 + o] + red[6656 + o];
    float s7 = red[7168 + o] + red[7680 + o];
    return ((s0 + s1) + (s2 + s3)) + ((s4 + s5) + (s6 + s7));
}

__global__ void __launch_bounds__(NTHR, 1)
rnn_kernel(const float* __restrict__ ec3input,
           const float* __restrict__ ec3_last,
           const float* __restrict__ ec5_last,
           const float* __restrict__ ca1_last,
           const float* __restrict__ ca1bias,
           const float* __restrict__ wca3ca1,
           const float* __restrict__ wec3ca1,
           const float* __restrict__ wca1ec5,
           const float* __restrict__ wca1act,
           const float* __restrict__ actbias,
           const void* __restrict__ noise_mask,
           const int* __restrict__ ca3order,
           float* __restrict__ out) {
    extern __shared__ float smem[];
    float* W1s = smem + SM_W1;
    float* W2s = smem + SM_W2;
    float* x_s = smem + SM_X;     // ec3 tile, then (aliased) ca1 tile
    float* red = smem + SM_RED;
    __shared__ int s_mmode;

    const int tid = threadIdx.x;
    const int bx  = blockIdx.x;
    const int g   = bx >> 4;
    const int ci  = bx & 15;
    const int j0  = ci * NC;
    const int r   = tid >> 5;        // row 0..15
    const int j   = tid & 31;
    const int lane = tid & 31;
    const int b   = g * RPG + r;
    const int col = j0 + j;

    // reset this group's phase counters (ordered by the grid barrier below)
    if (ci == 0 && tid < 2) g_pcnt[g * 2 + tid] = 0u;

    // ---------------- Phase 0a: mask-dtype scan ----------------
    if (tid == 0) g_scan[bx] = 0;
    __syncthreads();
    {
        const uint4* mw = (const uint4*)noise_mask;
        int bits = 0;
#pragma unroll
        for (int u = 0; u < 16; u++) {
            uint4 w = __ldcg(&mw[(size_t)bx * 8192 + (size_t)u * 512 + tid]);
            unsigned ws[4] = {w.x, w.y, w.z, w.w};
#pragma unroll
            for (int e = 0; e < 4; e++) {
                unsigned v = ws[e];
                if (v) {
                    if (v == 1u)               bits |= 2;
                    else if (v == 0x3F800000u) bits |= 4;
                    else                       bits |= 1;
                }
            }
        }
        if (bits) atomicOr(&g_scan[bx], bits);
    }

    // ---------------- Phase 0b: ca3drive precompute ----------------
    {
        float* ca3v = red;               // scratch (2048 of 8192 floats)
        const float stepv = 614.4f / 511.0f;
        const int   ordc  = ca3order[tid];
        const float cen   = -51.2f + stepv * (float)ordc;
#pragma unroll
        for (int i = 0; i < 4; i++) {
            float d = cen - (float)(4 * bx + i);
            ca3v[i * 512 + tid] = expf(-d * d * 0.02f);
        }
        __syncthreads();
        float a0 = 0.f, a1 = 0.f, a2 = 0.f, a3 = 0.f;
#pragma unroll 4
        for (int c = 0; c < 512; c++) {
            float wv = wca3ca1[c * 512 + tid];
            a0 = fmaf(ca3v[c],        wv, a0);
            a1 = fmaf(ca3v[512 + c],  wv, a1);
            a2 = fmaf(ca3v[1024 + c], wv, a2);
            a3 = fmaf(ca3v[1536 + c], wv, a3);
        }
        g_drive[(4 * bx + 0) * 512 + tid] = a0;
        g_drive[(4 * bx + 1) * 512 + tid] = a1;
        g_drive[(4 * bx + 2) * 512 + tid] = a2;
        g_drive[(4 * bx + 3) * 512 + tid] = a3;
    }
    grid_barrier(8, 128);

    if (tid == 0) {
        int bits = 0;
        for (int i = 0; i < 128; i++) bits |= __ldcg(&g_scan[i]);
        s_mmode = (bits & 1) ? 0 : ((bits & 4) ? 2 : ((bits & 2) ? 1 : 0));
    }
    __syncthreads();
    const int mmode = s_mmode;
    const uint8_t* nm_u8  = (const uint8_t*)noise_mask;
    const int*     nm_i32 = (const int*)noise_mask;
    const float*   nm_f32 = (const float*)noise_mask;

    // ---------------- Load weights + init state ----------------
    for (int idx = tid; idx < 512 * NC; idx += NTHR) {
        int kk = idx >> 5, jj = idx & 31;
        W1s[idx] = wec3ca1[kk * 512 + j0 + jj];
        W2s[idx] = wca1ec5[kk * 512 + j0 + jj];
    }
    const float bias_r = ca1bias[col];
    const float wact0  = wca1act[col * 2];
    const float wact1  = wca1act[col * 2 + 1];
    const float actb0  = actbias[0];
    const float actb1  = actbias[1];
    for (int u = tid; u < RPG * 128; u += NTHR) {
        int rr = u >> 7, kk = (u & 127) << 2;
        *(float4*)(x_s + rr * RPAD + kk) =
            *(const float4*)(ec3_last + (g * RPG + rr) * 512 + kk);
    }
    float ec5v = ec5_last[b * 512 + col];
    float ec3v = ec3_last[b * 512 + col];
    float ca1v = 0.f;
    __syncthreads();

    const int slotA = g * 2, slotB = g * 2 + 1;

    // ---------------- Main scan ----------------
    for (int t = 0; t < T; t++) {
        const unsigned tgt = (unsigned)(CPG * (t + 1));
        const size_t si = (size_t)(b * T + t) * 512 + col;
        float drv = __ldcg(&g_drive[t * 512 + col]);
        float xin = ec3input[si];
        bool  msk = (mmode == 0) ? (nm_u8[si] != 0)
                  : (mmode == 1) ? (nm_i32[si] != 0)
                                 : (nm_f32[si] != 0.0f);

        // ---- Phase A: ca1 = clip(drive * (1 + sigmoid(ec3 @ W1)) - bias) ----
        float z  = gemm_zval(W1s, x_s, red);
        float sg = __fdividef(1.f, 1.f + __expf(-z));
        ca1v = drv * (1.f + sg) - bias_r;
        ca1v = fminf(fmaxf(ca1v, 0.f), 1.f);
        g_ex_ca1[b * 512 + col] = ca1v;

        // act partials for this CTA's 32 columns (warp reduce)
        {
            float p0 = ca1v * wact0, p1 = ca1v * wact1;
#pragma unroll
            for (int o = 16; o; o >>= 1) {
                p0 += __shfl_down_sync(0xffffffffu, p0, o);
                p1 += __shfl_down_sync(0xffffffffu, p1, o);
            }
            if (lane == 0) {
                float2 pv; pv.x = p0; pv.y = p1;
                *(float2*)&g_ex_act[(b * CPG + ci) * 2] = pv;
            }
        }
        p_arrive(slotA);
        out[CA1HIS + si] = ca1v;        // hidden in arrive->wait gap
        p_wait(slotA, tgt);

        // act partial prefetch (issues early; reduced after arrive(slotB),
        // off the inter-barrier critical path)
        float2 actp; actp.x = 0.f; actp.y = 0.f;
        if (ci == 0 && lane < 16)
            actp = __ldcg((const float2*)&g_ex_act[(b * CPG + lane) * 2]);

        // gather full ca1 rows into x_s (aliased; ec3 tile is dead)
#pragma unroll
        for (int u = tid; u < RPG * 128; u += NTHR) {
            int rr = u >> 7, kk = (u & 127) << 2;
            *(float4*)(x_s + rr * RPAD + kk) =
                __ldcg((const float4*)(g_ex_ca1 + (g * RPG + rr) * 512 + kk));
        }
        __syncthreads();

        // ---- Phase B: ec5/ec3 update ----
        float z2 = gemm_zval(W2s, x_s, red);
        float e5 = ec5v + z2;
        e5 = 0.69f + 0.3f * __fdividef(1.f, 1.f + __expf(-4.f * (e5 - 0.3f)));
        float e3 = e5 * ec3v + 0.6f * (1.f - ec3v) * xin;
        if (msk) e3 = 0.5f * e3 + 0.3f;
        ec5v = e5; ec3v = e3;
        g_ex_ec3[b * 512 + col] = e3;
        p_arrive(slotB);

        // everything below is hidden in the arrive(B)->wait(B) gap
        out[EC3HIS + si] = e3;
        out[EC5HIS + si] = e5;
        if (ci == 0 && lane < 16) {     // act finish (off critical path)
            float a0 = actp.x, a1 = actp.y;
#pragma unroll
            for (int o = 8; o; o >>= 1) {
                a0 += __shfl_down_sync(0xffffu, a0, o);
                a1 += __shfl_down_sync(0xffffu, a1, o);
            }
            if (lane == 0) {
                out[ACT_OFF + (b * T + t) * 2 + 0] = a0 + actb0;
                out[ACT_OFF + (b * T + t) * 2 + 1] = a1 + actb1;
            }
        }

        if (t + 1 < T) {                // final step: no more consumers
            p_wait(slotB, tgt);
            // gather full new ec3 rows into x_s
#pragma unroll
            for (int u = tid; u < RPG * 128; u += NTHR) {
                int rr = u >> 7, kk = (u & 127) << 2;
                *(float4*)(x_s + rr * RPAD + kk) =
                    __ldcg((const float4*)(g_ex_ec3 + (g * RPG + rr) * 512 + kk));
            }
            __syncthreads();
        }
    }

    // ---------------- Finals ----------------
    out[EC3F + b * 512 + col] = ec3v;
    out[EC5F + b * 512 + col] = ec5v;
    out[CA1F + b * 512 + col] = ca1v;
}

extern "C" void kernel_launch(void* const* d_in, const int* in_sizes, int n_in,
                              void* d_out, int out_size) {
    (void)in_sizes; (void)n_in; (void)out_size;
    cudaFuncSetAttribute(rnn_kernel, cudaFuncAttributeMaxDynamicSharedMemorySize,
                         SMEM_BYTES);
    rnn_kernel<<<NGRP * CPG, NTHR, SMEM_BYTES>>>(
        (const float*)d_in[0],      // ec3input
        (const float*)d_in[1],      // ec3_last
        (const float*)d_in[2],      // ec5_last
        (const float*)d_in[3],      // ca1_last (unused)
        (const float*)d_in[4],      // ca1bias
        (const float*)d_in[5],      // wca3ca1
        (const float*)d_in[6],      // wec3ca1
        (const float*)d_in[7],      // wca1ec5
        (const float*)d_in[8],      // wca1act
        (const float*)d_in[9],      // actbias
        d_in[10],                   // noise_mask (encoding auto-detected)
        (const int*)d_in[11],       // ca3order
        (float*)d_out);
}